// round 7
// baseline (speedup 1.0000x reference)
#include <cuda_runtime.h>
#include <cuda_bf16.h>
#include <math.h>
#include <stdint.h>

// ---------------------------------------------------------------------------
// WindowAttention (Swin-V2) on GB300 — mma.sync bf16-split GEMMs with
// pre-split bf16 operands + shfl-PV attention.
// ---------------------------------------------------------------------------

#define BW   512
#define NTOK 144
#define DIM  512
#define NH   16
#define HD   32
#define NWIN 64
#define KDIM 512
#define XN   ((size_t)BW * NTOK * DIM)       // 37748736

// device scratch — referenced ONLY from device code (host shadow-ptr trap)
__device__ float g_q[(size_t)BW * NH * NTOK * HD];
__device__ float g_k[(size_t)BW * NH * NTOK * HD];
__device__ float g_v[(size_t)BW * NH * NTOK * HD];
__device__ float g_cpb[NH * 529];

// pre-split bf16 operands
__device__ __nv_bfloat16 g_xhi[XN],  g_xlo[XN];        // x
__device__ __nv_bfloat16 g_ohi[XN],  g_olo[XN];        // attention output
__device__ __nv_bfloat16 g_wqhi[3 * DIM * KDIM], g_wqlo[3 * DIM * KDIM];
__device__ __nv_bfloat16 g_wphi[DIM * KDIM],     g_wplo[DIM * KDIM];

static __device__ __forceinline__ uint32_t smem_u32(const void* p) {
    uint32_t a;
    asm("{ .reg .u64 t; cvta.to.shared.u64 t, %1; cvt.u32.u64 %0, t; }"
        : "=r"(a) : "l"(p));
    return a;
}

#define LDM4(r, addr) \
    asm volatile("ldmatrix.sync.aligned.m8n8.x4.shared.b16 {%0,%1,%2,%3}, [%4];" \
                 : "=r"((r)[0]), "=r"((r)[1]), "=r"((r)[2]), "=r"((r)[3]) \
                 : "r"(addr))

#define MMA16816(d, a, b0, b1) \
    asm volatile("mma.sync.aligned.m16n8k16.row.col.f32.bf16.bf16.f32 " \
                 "{%0,%1,%2,%3}, {%4,%5,%6,%7}, {%8,%9}, {%0,%1,%2,%3};" \
                 : "+f"((d)[0]), "+f"((d)[1]), "+f"((d)[2]), "+f"((d)[3]) \
                 : "r"((a)[0]), "r"((a)[1]), "r"((a)[2]), "r"((a)[3]), \
                   "r"(b0), "r"(b1))

// ---------------------------------------------------------------------------
// splitter: float -> bf16 hi + residual lo, grid-stride over float4
// SEL: 0 = x, 1 = w_qkv, 2 = w_proj
// ---------------------------------------------------------------------------
template <int SEL>
__global__ void split_kernel(const float* __restrict__ src, int n4)
{
    __nv_bfloat16* dhi = (SEL == 0) ? g_xhi : (SEL == 1) ? g_wqhi : g_wphi;
    __nv_bfloat16* dlo = (SEL == 0) ? g_xlo : (SEL == 1) ? g_wqlo : g_wplo;
    for (int i = blockIdx.x * blockDim.x + threadIdx.x; i < n4;
         i += gridDim.x * blockDim.x) {
        float4 v = ((const float4*)src)[i];
        __nv_bfloat16 h0 = __float2bfloat16(v.x);
        __nv_bfloat16 h1 = __float2bfloat16(v.y);
        __nv_bfloat16 h2 = __float2bfloat16(v.z);
        __nv_bfloat16 h3 = __float2bfloat16(v.w);
        ((ushort4*)dhi)[i] = make_ushort4(
            __bfloat16_as_ushort(h0), __bfloat16_as_ushort(h1),
            __bfloat16_as_ushort(h2), __bfloat16_as_ushort(h3));
        ((ushort4*)dlo)[i] = make_ushort4(
            __bfloat16_as_ushort(__float2bfloat16(v.x - __bfloat162float(h0))),
            __bfloat16_as_ushort(__float2bfloat16(v.y - __bfloat162float(h1))),
            __bfloat16_as_ushort(__float2bfloat16(v.z - __bfloat162float(h2))),
            __bfloat16_as_ushort(__float2bfloat16(v.w - __bfloat162float(h3))));
    }
}

// ---------------------------------------------------------------------------
// CPB MLP
// ---------------------------------------------------------------------------
__global__ void cpb_kernel(const float* __restrict__ w1,
                           const float* __restrict__ b1,
                           const float* __restrict__ w2)
{
    int idx = blockIdx.x * 128 + threadIdx.x;
    if (idx >= 529) return;
    int a = idx / 23, bb = idx % 23;
    float ta = (float)(a - 11) * (8.0f / 11.0f);
    float tb = (float)(bb - 11) * (8.0f / 11.0f);
    float t0 = copysignf(log2f(fabsf(ta) + 1.0f) * (1.0f / 3.0f), ta);
    float t1 = copysignf(log2f(fabsf(tb) + 1.0f) * (1.0f / 3.0f), tb);

    float acc[NH];
#pragma unroll
    for (int h = 0; h < NH; h++) acc[h] = 0.0f;
    for (int k = 0; k < 512; k++) {
        float hid = fmaf(t0, w1[2 * k], fmaf(t1, w1[2 * k + 1], b1[k]));
        hid = fmaxf(hid, 0.0f);
#pragma unroll
        for (int h = 0; h < NH; h++) acc[h] = fmaf(hid, w2[h * 512 + k], acc[h]);
    }
#pragma unroll
    for (int h = 0; h < NH; h++)
        g_cpb[h * 529 + idx] = 16.0f / (1.0f + __expf(-acc[h]));
}

// ---------------------------------------------------------------------------
// mma.sync GEMM on pre-split bf16: C = A @ W^T, 3-pass Markidis.
// CTA 128x128, BK=16, 32 chunks, double-buffered static smem (32KB).
// Hot loop: 4x LDG.128 + 4x STS.128 + ldmatrix + MMA (no conversion).
// MODE 0: A=g_xhi/lo, W=g_wqhi/lo, scatter epilogue -> g_q/g_k/g_v (+bias)
// MODE 1: A=g_ohi/lo, W=g_wphi/lo, C[r][c] = acc + biasA[c]
// ---------------------------------------------------------------------------
#define CHUNKS 32
#define STG 16384

template <int MODE>
__global__ __launch_bounds__(256)
void gemm_b(const float* __restrict__ biasA, const float* __restrict__ biasB,
            float* __restrict__ C)
{
    const __nv_bfloat16* __restrict__ Ahi = (MODE == 0) ? g_xhi : g_ohi;
    const __nv_bfloat16* __restrict__ Alo = (MODE == 0) ? g_xlo : g_olo;
    const __nv_bfloat16* __restrict__ Whi = (MODE == 0) ? g_wqhi : g_wphi;
    const __nv_bfloat16* __restrict__ Wlo = (MODE == 0) ? g_wqlo : g_wplo;

    __shared__ __align__(16) unsigned char sb[2][STG];

    const int tid = threadIdx.x;
    const int lane = tid & 31;
    const int w = tid >> 5;
    const int wm = w & 1;
    const int wn = w >> 1;
    const int m0 = blockIdx.y * 128;
    const int n0 = blockIdx.x * 128;

    float acc[4][4][4];
#pragma unroll
    for (int i = 0; i < 4; i++)
#pragma unroll
        for (int j = 0; j < 4; j++)
#pragma unroll
            for (int r = 0; r < 4; r++) acc[i][j][r] = 0.0f;

    // loader: thread -> (row = tid>>1, kseg = tid&1); one uint4 (8 bf16) per tile
    const int row = tid >> 1;
    const int kseg = tid & 1;
    const int aoff = (row >> 4) * 512 + (kseg * 2 + ((row >> 3) & 1)) * 128
                   + (row & 7) * 16;
    const int boff = (row >> 4) * 512 + (((row >> 3) & 1) * 2 + kseg) * 128
                   + (row & 7) * 16;
    const size_t ga = (size_t)(m0 + row) * KDIM + kseg * 8;
    const size_t gb = (size_t)(n0 + row) * KDIM + kseg * 8;

    uint4 rah, ral, rbh, rbl;
    auto load_gmem = [&](int c) {
        rah = *(const uint4*)&Ahi[ga + c * 16];
        ral = *(const uint4*)&Alo[ga + c * 16];
        rbh = *(const uint4*)&Whi[gb + c * 16];
        rbl = *(const uint4*)&Wlo[gb + c * 16];
    };
    auto store_stage = [&](int st) {
        unsigned char* base = sb[st];
        *(uint4*)(base + aoff)         = rah;
        *(uint4*)(base + 4096 + aoff)  = ral;
        *(uint4*)(base + 8192 + boff)  = rbh;
        *(uint4*)(base + 12288 + boff) = rbl;
    };

    const uint32_t lmoff = (uint32_t)((lane >> 3) * 128 + (lane & 7) * 16);

    auto compute_stage = [&](int st) {
        uint32_t sbase = smem_u32(sb[st]);
        uint32_t a_lm = sbase + (uint32_t)(wm * 4) * 512u + lmoff;
        uint32_t b_lm = sbase + 8192u + (uint32_t)(wn * 2) * 512u + lmoff;

        uint32_t ahi[4][4], alo[4][4], bhi[2][4], blo[2][4];
#pragma unroll
        for (int ti = 0; ti < 4; ti++) LDM4(ahi[ti], a_lm + ti * 512);
#pragma unroll
        for (int g = 0; g < 2; g++) LDM4(bhi[g], b_lm + g * 512);
#pragma unroll
        for (int ti = 0; ti < 4; ti++)
#pragma unroll
            for (int tj = 0; tj < 4; tj++)
                MMA16816(acc[ti][tj], ahi[ti],
                         bhi[tj >> 1][(tj & 1) * 2], bhi[tj >> 1][(tj & 1) * 2 + 1]);
#pragma unroll
        for (int g = 0; g < 2; g++) LDM4(blo[g], b_lm + 4096 + g * 512);
#pragma unroll
        for (int ti = 0; ti < 4; ti++)
#pragma unroll
            for (int tj = 0; tj < 4; tj++)
                MMA16816(acc[ti][tj], ahi[ti],
                         blo[tj >> 1][(tj & 1) * 2], blo[tj >> 1][(tj & 1) * 2 + 1]);
#pragma unroll
        for (int ti = 0; ti < 4; ti++) LDM4(alo[ti], a_lm + 4096 + ti * 512);
#pragma unroll
        for (int ti = 0; ti < 4; ti++)
#pragma unroll
            for (int tj = 0; tj < 4; tj++)
                MMA16816(acc[ti][tj], alo[ti],
                         bhi[tj >> 1][(tj & 1) * 2], bhi[tj >> 1][(tj & 1) * 2 + 1]);
    };

    load_gmem(0);
    store_stage(0);
    __syncthreads();

#pragma unroll 2
    for (int c = 0; c < CHUNKS; c++) {
        if (c + 1 < CHUNKS) load_gmem(c + 1);
        compute_stage(c & 1);
        if (c + 1 < CHUNKS) store_stage((c + 1) & 1);
        __syncthreads();
    }

#pragma unroll
    for (int ti = 0; ti < 4; ti++) {
#pragma unroll
        for (int half = 0; half < 2; half++) {
            int m = m0 + wm * 64 + ti * 16 + (lane >> 2) + half * 8;
            int bwin = 0, nt = 0;
            if (MODE == 0) { bwin = m / NTOK; nt = m - bwin * NTOK; }
#pragma unroll
            for (int tj = 0; tj < 4; tj++) {
                int n = n0 + wn * 32 + tj * 8 + (lane & 3) * 2;
                float v0 = acc[ti][tj][half * 2 + 0];
                float v1 = acc[ti][tj][half * 2 + 1];
                if (MODE == 0) {
                    int which = n >> 9;
                    int cc = n & 511;
                    int hh = cc >> 5;
                    int dd = cc & 31;
                    float b0 = (which == 0) ? biasA[cc]
                             : (which == 2 ? biasB[cc] : 0.0f);
                    float b1 = (which == 0) ? biasA[cc + 1]
                             : (which == 2 ? biasB[cc + 1] : 0.0f);
                    float* dst = (which == 0) ? g_q : (which == 1 ? g_k : g_v);
                    *(float2*)&dst[((((size_t)bwin * NH + hh) * NTOK) + nt) * HD + dd] =
                        make_float2(v0 + b0, v1 + b1);
                } else {
                    *(float2*)&C[(size_t)m * DIM + n] =
                        make_float2(v0 + biasA[n], v1 + biasA[n + 1]);
                }
            }
        }
    }
}

// ---------------------------------------------------------------------------
// Attention: one block per (b,h), 8 warps, 4 rows per warp-iteration.
// PV uses shfl broadcast of score registers (no prob smem). Output written
// directly as bf16 hi/lo split for the proj GEMM.
// smem: kn 18KB + vv 18KB + bs 2116B = 39KB static.
// ---------------------------------------------------------------------------
__global__ __launch_bounds__(256)
void attn_kernel(const float* __restrict__ mask,
                 const float* __restrict__ logit_scale)
{
    __shared__ float kn[NTOK * 32];
    __shared__ float vv[NTOK * 32];
    __shared__ float bs[529];

    int bid = blockIdx.x;
    int b = bid >> 4;
    int h = bid & 15;
    int tid = threadIdx.x;
    int w = tid >> 5;
    int lane = tid & 31;

    for (int t = tid; t < 529; t += 256) bs[t] = g_cpb[h * 529 + t];

    size_t base = (size_t)bid * (NTOK * HD);
    for (int t = tid; t < NTOK * 32; t += 256) {
        int row = t >> 5;
        int d = t & 31;
        int sw = row * 32 + (d ^ (row & 31));
        kn[sw] = g_k[base + t];
        vv[sw] = g_v[base + t];
    }
    __syncthreads();

    if (tid < NTOK) {
        int sx = tid & 31;
        float ss = 0.0f;
#pragma unroll
        for (int d = 0; d < HD; d++) {
            float kv = kn[tid * 32 + (d ^ sx)];
            ss = fmaf(kv, kv, ss);
        }
        float inv = 1.0f / fmaxf(sqrtf(ss), 1e-12f);
#pragma unroll
        for (int d = 0; d < HD; d++)
            kn[tid * 32 + (d ^ sx)] *= inv;
    }
    __syncthreads();

    float scale = __expf(fminf(logit_scale[h], 4.605170185988092f));
    const float* mbase = mask + (size_t)(b & (NWIN - 1)) * (NTOK * NTOK);

    // 36 groups of 4 rows, strided over 8 warps
    for (int g = w; g < 36; g += 8) {
        int i0 = 4 * g;
        int yi[4], xi[4];
#pragma unroll
        for (int r = 0; r < 4; r++) {
            yi[r] = (i0 + r) / 12;
            xi[r] = (i0 + r) - yi[r] * 12;
        }

        // load + normalize 4 q rows (lane = d)
        float q[4], ssq[4];
#pragma unroll
        for (int r = 0; r < 4; r++) {
            q[r] = g_q[base + (size_t)(i0 + r) * HD + lane];
            ssq[r] = q[r] * q[r];
        }
#pragma unroll
        for (int off = 16; off; off >>= 1)
#pragma unroll
            for (int r = 0; r < 4; r++)
                ssq[r] += __shfl_xor_sync(0xffffffffu, ssq[r], off);
#pragma unroll
        for (int r = 0; r < 4; r++)
            q[r] *= scale / fmaxf(sqrtf(ssq[r]), 1e-12f);

        float s[4][5];
#pragma unroll
        for (int r = 0; r < 4; r++)
#pragma unroll
            for (int t = 0; t < 5; t++) s[r][t] = 0.0f;

#pragma unroll
        for (int d = 0; d < HD; d++) {
            float qa[4];
#pragma unroll
            for (int r = 0; r < 4; r++)
                qa[r] = __shfl_sync(0xffffffffu, q[r], d);
#pragma unroll
            for (int t = 0; t < 5; t++) {
                int j = lane + 32 * t;
                int jc = (j < NTOK) ? j : (NTOK - 1);
                float kv = kn[jc * 32 + (d ^ (jc & 31))];
#pragma unroll
                for (int r = 0; r < 4; r++)
                    s[r][t] = fmaf(qa[r], kv, s[r][t]);
            }
        }

        float mx[4] = { -1e30f, -1e30f, -1e30f, -1e30f };
#pragma unroll
        for (int t = 0; t < 5; t++) {
            int j = lane + 32 * t;
            if (j < NTOK) {
                int yj = j / 12, xj = j - yj * 12;
#pragma unroll
                for (int r = 0; r < 4; r++) {
                    float bv = bs[(yi[r] - yj + 11) * 23 + (xi[r] - xj + 11)];
                    s[r][t] += bv + mbase[(i0 + r) * NTOK + j];
                    mx[r] = fmaxf(mx[r], s[r][t]);
                }
            }
        }
#pragma unroll
        for (int off = 16; off; off >>= 1)
#pragma unroll
            for (int r = 0; r < 4; r++)
                mx[r] = fmaxf(mx[r], __shfl_xor_sync(0xffffffffu, mx[r], off));

        float sum[4] = { 0.0f, 0.0f, 0.0f, 0.0f };
#pragma unroll
        for (int t = 0; t < 5; t++) {
            int j = lane + 32 * t;
#pragma unroll
            for (int r = 0; r < 4; r++) {
                float p = (j < NTOK) ? __expf(s[r][t] - mx[r]) : 0.0f;
                s[r][t] = p;
                sum[r] += p;
            }
        }
#pragma unroll
        for (int off = 16; off; off >>= 1)
#pragma unroll
            for (int r = 0; r < 4; r++)
                sum[r] += __shfl_xor_sync(0xffffffffu, sum[r], off);

        // PV: broadcast probs via shfl; lane = d index
        float o[4] = { 0.0f, 0.0f, 0.0f, 0.0f };
#pragma unroll
        for (int t = 0; t < 4; t++) {
#pragma unroll
            for (int sl = 0; sl < 32; sl++) {
                int j = 32 * t + sl;
                float vval = vv[j * 32 + (lane ^ (j & 31))];
#pragma unroll
                for (int r = 0; r < 4; r++) {
                    float pj = __shfl_sync(0xffffffffu, s[r][t], sl);
                    o[r] = fmaf(pj, vval, o[r]);
                }
            }
        }
#pragma unroll
        for (int sl = 0; sl < 16; sl++) {       // t = 4: j = 128..143
            int j = 128 + sl;
            float vval = vv[j * 32 + (lane ^ (j & 31))];
#pragma unroll
            for (int r = 0; r < 4; r++) {
                float pj = __shfl_sync(0xffffffffu, s[r][4], sl);
                o[r] = fmaf(pj, vval, o[r]);
            }
        }

        size_t obase = ((size_t)b * NTOK) * DIM + h * HD + lane;
#pragma unroll
        for (int r = 0; r < 4; r++) {
            float val = o[r] / sum[r];
            __nv_bfloat16 hi = __float2bfloat16(val);
            __nv_bfloat16 lo = __float2bfloat16(val - __bfloat162float(hi));
            size_t oi = obase + (size_t)(i0 + r) * DIM;
            g_ohi[oi] = hi;
            g_olo[oi] = lo;
        }
    }
}

// ---------------------------------------------------------------------------
// launch — size-based input resolution (order-robust)
// ---------------------------------------------------------------------------
extern "C" void kernel_launch(void* const* d_in, const int* in_sizes, int n_in,
                              void* d_out, int out_size)
{
    int ix = 0, imask = 1, iwqkv = 2, ils = 5, iw1 = 6, iw2 = 8, iwproj = 9;
    int small[4] = {3, 4, 7, 10};
    int ns = 0;
    int sm_tmp[8];
    int fx = -1, fmask = -1, fwqkv = -1, fls = -1, fw1 = -1, fw2 = -1, fwp = -1;
    for (int i = 0; i < n_in; i++) {
        switch (in_sizes[i]) {
            case 37748736: fx = i; break;
            case 1327104:  fmask = i; break;
            case 786432:   fwqkv = i; break;
            case 16:       fls = i; break;
            case 1024:     fw1 = i; break;
            case 8192:     fw2 = i; break;
            case 262144:   fwp = i; break;
            case 512:      if (ns < 8) sm_tmp[ns++] = i; break;
            default: break;
        }
    }
    if (fx >= 0 && fmask >= 0 && fwqkv >= 0 && fls >= 0 && fw1 >= 0 &&
        fw2 >= 0 && fwp >= 0 && ns >= 4) {
        ix = fx; imask = fmask; iwqkv = fwqkv; ils = fls;
        iw1 = fw1; iw2 = fw2; iwproj = fwp;
        for (int t = 0; t < 4; t++) small[t] = sm_tmp[t];
    }

    const float* x           = (const float*)d_in[ix];
    const float* mask        = (const float*)d_in[imask];
    const float* w_qkv       = (const float*)d_in[iwqkv];
    const float* q_bias      = (const float*)d_in[small[0]];
    const float* v_bias      = (const float*)d_in[small[1]];
    const float* logit_scale = (const float*)d_in[ils];
    const float* w1          = (const float*)d_in[iw1];
    const float* b1          = (const float*)d_in[small[2]];
    const float* w2          = (const float*)d_in[iw2];
    const float* w_proj      = (const float*)d_in[iwproj];
    const float* b_proj      = (const float*)d_in[small[3]];
    float* out = (float*)d_out;
    (void)out_size;

    // 0) pre-split fp32 -> bf16 hi/lo
    split_kernel<0><<<4096, 256>>>(x, (int)(XN / 4));
    split_kernel<1><<<768, 256>>>(w_qkv, 3 * DIM * KDIM / 4);
    split_kernel<2><<<256, 256>>>(w_proj, DIM * KDIM / 4);

    // 1) CPB bias table
    cpb_kernel<<<5, 128>>>(w1, b1, w2);

    // 2) QKV: (73728 x 512) @ (1536 x 512)^T — pure-bf16 mma.sync
    {
        dim3 grid(1536 / 128, (BW * NTOK) / 128);
        gemm_b<0><<<grid, 256>>>(q_bias, v_bias, nullptr);
    }

    // 3) attention per (b,h) — writes split bf16 output
    attn_kernel<<<BW * NH, 256>>>(mask, logit_scale);

    // 4) proj: (73728 x 512) @ (512 x 512)^T — pure-bf16 mma.sync
    {
        dim3 grid(DIM / 128, (BW * NTOK) / 128);
        gemm_b<1><<<grid, 256>>>(b_proj, nullptr, out);
    }
}

// round 8
// speedup vs baseline: 1.2344x; 1.2344x over previous
#include <cuda_runtime.h>
#include <cuda_bf16.h>
#include <math.h>
#include <stdint.h>

// ---------------------------------------------------------------------------
// WindowAttention (Swin-V2) on GB300 — cp.async bf16-split mma.sync GEMMs,
// smem-probs attention, pre-split operands.
// ---------------------------------------------------------------------------

#define BW   512
#define NTOK 144
#define DIM  512
#define NH   16
#define HD   32
#define NWIN 64
#define KDIM 512
#define XN   ((size_t)BW * NTOK * DIM)       // 37748736

// device scratch — referenced ONLY from device code (host shadow-ptr trap)
__device__ float g_q[(size_t)BW * NH * NTOK * HD];
__device__ float g_k[(size_t)BW * NH * NTOK * HD];
__device__ float g_v[(size_t)BW * NH * NTOK * HD];
__device__ float g_cpb[NH * 529];

// pre-split bf16 operands
__device__ __nv_bfloat16 g_xhi[XN],  g_xlo[XN];        // x
__device__ __nv_bfloat16 g_ohi[XN],  g_olo[XN];        // attention output
__device__ __nv_bfloat16 g_wqhi[3 * DIM * KDIM], g_wqlo[3 * DIM * KDIM];
__device__ __nv_bfloat16 g_wphi[DIM * KDIM],     g_wplo[DIM * KDIM];

static __device__ __forceinline__ uint32_t smem_u32(const void* p) {
    uint32_t a;
    asm("{ .reg .u64 t; cvta.to.shared.u64 t, %1; cvt.u32.u64 %0, t; }"
        : "=r"(a) : "l"(p));
    return a;
}

#define LDM4(r, addr) \
    asm volatile("ldmatrix.sync.aligned.m8n8.x4.shared.b16 {%0,%1,%2,%3}, [%4];" \
                 : "=r"((r)[0]), "=r"((r)[1]), "=r"((r)[2]), "=r"((r)[3]) \
                 : "r"(addr))

#define MMA16816(d, a, b0, b1) \
    asm volatile("mma.sync.aligned.m16n8k16.row.col.f32.bf16.bf16.f32 " \
                 "{%0,%1,%2,%3}, {%4,%5,%6,%7}, {%8,%9}, {%0,%1,%2,%3};" \
                 : "+f"((d)[0]), "+f"((d)[1]), "+f"((d)[2]), "+f"((d)[3]) \
                 : "r"((a)[0]), "r"((a)[1]), "r"((a)[2]), "r"((a)[3]), \
                   "r"(b0), "r"(b1))

#define CP_ASYNC16(saddr, gptr) \
    asm volatile("cp.async.cg.shared.global [%0], [%1], 16;" \
                 :: "r"(saddr), "l"(gptr))
#define CP_COMMIT() asm volatile("cp.async.commit_group;" ::: "memory")
#define CP_WAIT1()  asm volatile("cp.async.wait_group 1;" ::: "memory")

// ---------------------------------------------------------------------------
// splitter: float -> bf16 hi + residual lo
// SEL: 0 = x, 1 = w_qkv, 2 = w_proj
// ---------------------------------------------------------------------------
template <int SEL>
__global__ void split_kernel(const float* __restrict__ src, int n4)
{
    __nv_bfloat16* dhi = (SEL == 0) ? g_xhi : (SEL == 1) ? g_wqhi : g_wphi;
    __nv_bfloat16* dlo = (SEL == 0) ? g_xlo : (SEL == 1) ? g_wqlo : g_wplo;
    for (int i = blockIdx.x * blockDim.x + threadIdx.x; i < n4;
         i += gridDim.x * blockDim.x) {
        float4 v = ((const float4*)src)[i];
        __nv_bfloat16 h0 = __float2bfloat16(v.x);
        __nv_bfloat16 h1 = __float2bfloat16(v.y);
        __nv_bfloat16 h2 = __float2bfloat16(v.z);
        __nv_bfloat16 h3 = __float2bfloat16(v.w);
        ((ushort4*)dhi)[i] = make_ushort4(
            __bfloat16_as_ushort(h0), __bfloat16_as_ushort(h1),
            __bfloat16_as_ushort(h2), __bfloat16_as_ushort(h3));
        ((ushort4*)dlo)[i] = make_ushort4(
            __bfloat16_as_ushort(__float2bfloat16(v.x - __bfloat162float(h0))),
            __bfloat16_as_ushort(__float2bfloat16(v.y - __bfloat162float(h1))),
            __bfloat16_as_ushort(__float2bfloat16(v.z - __bfloat162float(h2))),
            __bfloat16_as_ushort(__float2bfloat16(v.w - __bfloat162float(h3))));
    }
}

// ---------------------------------------------------------------------------
// CPB MLP — one block per table entry, 128 threads split K, reduce.
// ---------------------------------------------------------------------------
__global__ __launch_bounds__(128)
void cpb_kernel(const float* __restrict__ w1,
                const float* __restrict__ b1,
                const float* __restrict__ w2)
{
    __shared__ float part[4][NH];
    int idx = blockIdx.x;              // 0..528
    int tid = threadIdx.x;
    int lane = tid & 31;
    int w = tid >> 5;

    int a = idx / 23, bb = idx % 23;
    float ta = (float)(a - 11) * (8.0f / 11.0f);
    float tb = (float)(bb - 11) * (8.0f / 11.0f);
    float t0 = copysignf(log2f(fabsf(ta) + 1.0f) * (1.0f / 3.0f), ta);
    float t1 = copysignf(log2f(fabsf(tb) + 1.0f) * (1.0f / 3.0f), tb);

    float acc[NH];
#pragma unroll
    for (int h = 0; h < NH; h++) acc[h] = 0.0f;
#pragma unroll
    for (int kk = 0; kk < 4; kk++) {
        int k = tid + kk * 128;
        float hid = fmaf(t0, w1[2 * k], fmaf(t1, w1[2 * k + 1], b1[k]));
        hid = fmaxf(hid, 0.0f);
#pragma unroll
        for (int h = 0; h < NH; h++) acc[h] = fmaf(hid, w2[h * 512 + k], acc[h]);
    }
#pragma unroll
    for (int off = 16; off; off >>= 1)
#pragma unroll
        for (int h = 0; h < NH; h++)
            acc[h] += __shfl_xor_sync(0xffffffffu, acc[h], off);
    if (lane == 0)
#pragma unroll
        for (int h = 0; h < NH; h++) part[w][h] = acc[h];
    __syncthreads();
    if (tid < NH) {
        float s = part[0][tid] + part[1][tid] + part[2][tid] + part[3][tid];
        g_cpb[tid * 529 + idx] = 16.0f / (1.0f + __expf(-s));
    }
}

// ---------------------------------------------------------------------------
// cp.async 3-stage mma.sync GEMM on pre-split bf16: C = A @ W^T (3-pass).
// CTA 128x128, BK=16, 32 chunks. smem = 3 stages x 16KB = 48KB static.
// MODE 0: A=g_xhi/lo, W=g_wqhi/lo -> scatter g_q/g_k/g_v (+bias)
// MODE 1: A=g_ohi/lo, W=g_wphi/lo -> C[r][c] = acc + biasA[c]
// ---------------------------------------------------------------------------
#define CHUNKS 32
#define STG 16384
#define NSTAGE 3

template <int MODE>
__global__ __launch_bounds__(256)
void gemm_b(const float* __restrict__ biasA, const float* __restrict__ biasB,
            float* __restrict__ C)
{
    const __nv_bfloat16* __restrict__ Ahi = (MODE == 0) ? g_xhi : g_ohi;
    const __nv_bfloat16* __restrict__ Alo = (MODE == 0) ? g_xlo : g_olo;
    const __nv_bfloat16* __restrict__ Whi = (MODE == 0) ? g_wqhi : g_wphi;
    const __nv_bfloat16* __restrict__ Wlo = (MODE == 0) ? g_wqlo : g_wplo;

    __shared__ __align__(16) unsigned char sb[NSTAGE][STG];

    const int tid = threadIdx.x;
    const int lane = tid & 31;
    const int w = tid >> 5;
    const int wm = w & 1;
    const int wn = w >> 1;
    const int m0 = blockIdx.y * 128;
    const int n0 = blockIdx.x * 128;

    float acc[4][4][4];
#pragma unroll
    for (int i = 0; i < 4; i++)
#pragma unroll
        for (int j = 0; j < 4; j++)
#pragma unroll
            for (int r = 0; r < 4; r++) acc[i][j][r] = 0.0f;

    // loader: thread -> (row = tid>>1, kseg = tid&1); one 16B vec per tile
    const int row = tid >> 1;
    const int kseg = tid & 1;
    const int aoff = (row >> 4) * 512 + (kseg * 2 + ((row >> 3) & 1)) * 128
                   + (row & 7) * 16;
    const int boff = (row >> 4) * 512 + (((row >> 3) & 1) * 2 + kseg) * 128
                   + (row & 7) * 16;
    const size_t ga = (size_t)(m0 + row) * KDIM + kseg * 8;
    const size_t gb = (size_t)(n0 + row) * KDIM + kseg * 8;

    auto issue_stage = [&](int c, int st) {
        uint32_t s = smem_u32(sb[st]);
        CP_ASYNC16(s + aoff,         (const char*)&Ahi[ga + c * 16]);
        CP_ASYNC16(s + 4096 + aoff,  (const char*)&Alo[ga + c * 16]);
        CP_ASYNC16(s + 8192 + boff,  (const char*)&Whi[gb + c * 16]);
        CP_ASYNC16(s + 12288 + boff, (const char*)&Wlo[gb + c * 16]);
        CP_COMMIT();
    };

    const uint32_t lmoff = (uint32_t)((lane >> 3) * 128 + (lane & 7) * 16);

    auto compute_stage = [&](int st) {
        uint32_t sbase = smem_u32(sb[st]);
        uint32_t a_lm = sbase + (uint32_t)(wm * 4) * 512u + lmoff;
        uint32_t b_lm = sbase + 8192u + (uint32_t)(wn * 2) * 512u + lmoff;

        uint32_t ahi[4][4], alo[4][4], bhi[2][4], blo[2][4];
#pragma unroll
        for (int ti = 0; ti < 4; ti++) LDM4(ahi[ti], a_lm + ti * 512);
#pragma unroll
        for (int g = 0; g < 2; g++) LDM4(bhi[g], b_lm + g * 512);
#pragma unroll
        for (int ti = 0; ti < 4; ti++)
#pragma unroll
            for (int tj = 0; tj < 4; tj++)
                MMA16816(acc[ti][tj], ahi[ti],
                         bhi[tj >> 1][(tj & 1) * 2], bhi[tj >> 1][(tj & 1) * 2 + 1]);
#pragma unroll
        for (int g = 0; g < 2; g++) LDM4(blo[g], b_lm + 4096 + g * 512);
#pragma unroll
        for (int ti = 0; ti < 4; ti++)
#pragma unroll
            for (int tj = 0; tj < 4; tj++)
                MMA16816(acc[ti][tj], ahi[ti],
                         blo[tj >> 1][(tj & 1) * 2], blo[tj >> 1][(tj & 1) * 2 + 1]);
#pragma unroll
        for (int ti = 0; ti < 4; ti++) LDM4(alo[ti], a_lm + 4096 + ti * 512);
#pragma unroll
        for (int ti = 0; ti < 4; ti++)
#pragma unroll
            for (int tj = 0; tj < 4; tj++)
                MMA16816(acc[ti][tj], alo[ti],
                         bhi[tj >> 1][(tj & 1) * 2], bhi[tj >> 1][(tj & 1) * 2 + 1]);
    };

    // prologue: stages 0,1 in flight
    issue_stage(0, 0);
    issue_stage(1, 1);

    int st = 0, st2 = 2;
    for (int c = 0; c < CHUNKS; c++) {
        CP_WAIT1();            // stage c landed (<=1 group outstanding)
        __syncthreads();       // all warps past compute(c-1); safe to reuse st2
        compute_stage(st);
        if (c + 2 < CHUNKS) issue_stage(c + 2, st2);
        st = (st + 1 == NSTAGE) ? 0 : st + 1;
        st2 = (st2 + 1 == NSTAGE) ? 0 : st2 + 1;
    }

    // epilogue
#pragma unroll
    for (int ti = 0; ti < 4; ti++) {
#pragma unroll
        for (int half = 0; half < 2; half++) {
            int m = m0 + wm * 64 + ti * 16 + (lane >> 2) + half * 8;
            int bwin = 0, nt = 0;
            if (MODE == 0) { bwin = m / NTOK; nt = m - bwin * NTOK; }
#pragma unroll
            for (int tj = 0; tj < 4; tj++) {
                int n = n0 + wn * 32 + tj * 8 + (lane & 3) * 2;
                float v0 = acc[ti][tj][half * 2 + 0];
                float v1 = acc[ti][tj][half * 2 + 1];
                if (MODE == 0) {
                    int which = n >> 9;
                    int cc = n & 511;
                    int hh = cc >> 5;
                    int dd = cc & 31;
                    float b0 = (which == 0) ? biasA[cc]
                             : (which == 2 ? biasB[cc] : 0.0f);
                    float b1 = (which == 0) ? biasA[cc + 1]
                             : (which == 2 ? biasB[cc + 1] : 0.0f);
                    float* dst = (which == 0) ? g_q : (which == 1 ? g_k : g_v);
                    *(float2*)&dst[((((size_t)bwin * NH + hh) * NTOK) + nt) * HD + dd] =
                        make_float2(v0 + b0, v1 + b1);
                } else {
                    *(float2*)&C[(size_t)m * DIM + n] =
                        make_float2(v0 + biasA[n], v1 + biasA[n + 1]);
                }
            }
        }
    }
}

// ---------------------------------------------------------------------------
// Attention (R6-proven form): one block per (b,h), 8 warps, 2 rows/warp iter,
// smem probs. Output written as bf16 hi/lo split for the proj GEMM.
// ---------------------------------------------------------------------------
__global__ __launch_bounds__(256)
void attn_kernel(const float* __restrict__ mask,
                 const float* __restrict__ logit_scale)
{
    __shared__ float kn[NTOK * 32];
    __shared__ float vv[NTOK * 32];
    __shared__ float bs[529];
    __shared__ float ps[16 * NTOK];

    int bid = blockIdx.x;
    int b = bid >> 4;
    int h = bid & 15;
    int tid = threadIdx.x;
    int w = tid >> 5;
    int lane = tid & 31;

    for (int t = tid; t < 529; t += 256) bs[t] = g_cpb[h * 529 + t];

    size_t base = (size_t)bid * (NTOK * HD);
    for (int t = tid; t < NTOK * 32; t += 256) {
        int row = t >> 5;
        int d = t & 31;
        int sw = row * 32 + (d ^ (row & 31));
        kn[sw] = g_k[base + t];
        vv[sw] = g_v[base + t];
    }
    __syncthreads();

    if (tid < NTOK) {
        int sx = tid & 31;
        float ss = 0.0f;
#pragma unroll
        for (int d = 0; d < HD; d++) {
            float kv = kn[tid * 32 + (d ^ sx)];
            ss = fmaf(kv, kv, ss);
        }
        float inv = 1.0f / fmaxf(sqrtf(ss), 1e-12f);
#pragma unroll
        for (int d = 0; d < HD; d++)
            kn[tid * 32 + (d ^ sx)] *= inv;
    }
    __syncthreads();

    float scale = __expf(fminf(logit_scale[h], 4.605170185988092f));
    const float* mbase = mask + (size_t)(b & (NWIN - 1)) * (NTOK * NTOK);

    for (int ii = w; ii < 72; ii += 8) {
        int i0 = 2 * ii, i1 = i0 + 1;
        int yi0 = i0 / 12, xi0 = i0 - yi0 * 12;
        int yi1 = i1 / 12, xi1 = i1 - yi1 * 12;

        float q0 = g_q[base + (size_t)i0 * HD + lane];
        float q1 = g_q[base + (size_t)i1 * HD + lane];
        float ss0 = q0 * q0, ss1 = q1 * q1;
#pragma unroll
        for (int off = 16; off; off >>= 1) {
            ss0 += __shfl_xor_sync(0xffffffffu, ss0, off);
            ss1 += __shfl_xor_sync(0xffffffffu, ss1, off);
        }
        q0 *= scale / fmaxf(sqrtf(ss0), 1e-12f);
        q1 *= scale / fmaxf(sqrtf(ss1), 1e-12f);

        float s0[5], s1[5];
#pragma unroll
        for (int t = 0; t < 5; t++) { s0[t] = 0.0f; s1[t] = 0.0f; }

#pragma unroll
        for (int d = 0; d < HD; d++) {
            float qa = __shfl_sync(0xffffffffu, q0, d);
            float qb = __shfl_sync(0xffffffffu, q1, d);
#pragma unroll
            for (int t = 0; t < 5; t++) {
                int j = lane + 32 * t;
                int jc = (j < NTOK) ? j : (NTOK - 1);
                float kv = kn[jc * 32 + (d ^ (jc & 31))];
                s0[t] = fmaf(qa, kv, s0[t]);
                s1[t] = fmaf(qb, kv, s1[t]);
            }
        }

        float m0 = -1e30f, m1 = -1e30f;
#pragma unroll
        for (int t = 0; t < 5; t++) {
            int j = lane + 32 * t;
            if (j < NTOK) {
                int yj = j / 12, xj = j - yj * 12;
                float b0v = bs[(yi0 - yj + 11) * 23 + (xi0 - xj + 11)];
                float b1v = bs[(yi1 - yj + 11) * 23 + (xi1 - xj + 11)];
                s0[t] += b0v + mbase[i0 * NTOK + j];
                s1[t] += b1v + mbase[i1 * NTOK + j];
                m0 = fmaxf(m0, s0[t]);
                m1 = fmaxf(m1, s1[t]);
            } else {
                s0[t] = -1e30f;
                s1[t] = -1e30f;
            }
        }
#pragma unroll
        for (int off = 16; off; off >>= 1) {
            m0 = fmaxf(m0, __shfl_xor_sync(0xffffffffu, m0, off));
            m1 = fmaxf(m1, __shfl_xor_sync(0xffffffffu, m1, off));
        }
        float sum0 = 0.0f, sum1 = 0.0f;
#pragma unroll
        for (int t = 0; t < 5; t++) {
            int j = lane + 32 * t;
            if (j < NTOK) {
                float p0 = __expf(s0[t] - m0);
                float p1 = __expf(s1[t] - m1);
                s0[t] = p0; s1[t] = p1;
                sum0 += p0; sum1 += p1;
            }
        }
#pragma unroll
        for (int off = 16; off; off >>= 1) {
            sum0 += __shfl_xor_sync(0xffffffffu, sum0, off);
            sum1 += __shfl_xor_sync(0xffffffffu, sum1, off);
        }
        float r0 = 1.0f / sum0;
        float r1 = 1.0f / sum1;
        float* p0p = ps + (2 * w) * NTOK;
        float* p1p = p0p + NTOK;
#pragma unroll
        for (int t = 0; t < 5; t++) {
            int j = lane + 32 * t;
            if (j < NTOK) {
                p0p[j] = s0[t] * r0;
                p1p[j] = s1[t] * r1;
            }
        }
        __syncwarp();

        float o0 = 0.0f, o1 = 0.0f;
#pragma unroll 8
        for (int j = 0; j < NTOK; j++) {
            float vval = vv[j * 32 + (lane ^ (j & 31))];
            o0 = fmaf(p0p[j], vval, o0);
            o1 = fmaf(p1p[j], vval, o1);
        }
        size_t obase = ((size_t)b * NTOK) * DIM + h * HD + lane;
        {
            __nv_bfloat16 h0 = __float2bfloat16(o0);
            __nv_bfloat16 l0 = __float2bfloat16(o0 - __bfloat162float(h0));
            __nv_bfloat16 h1 = __float2bfloat16(o1);
            __nv_bfloat16 l1 = __float2bfloat16(o1 - __bfloat162float(h1));
            size_t oi0 = obase + (size_t)i0 * DIM;
            size_t oi1 = obase + (size_t)i1 * DIM;
            g_ohi[oi0] = h0; g_olo[oi0] = l0;
            g_ohi[oi1] = h1; g_olo[oi1] = l1;
        }
        __syncwarp();
    }
}

// ---------------------------------------------------------------------------
// launch — size-based input resolution (order-robust)
// ---------------------------------------------------------------------------
extern "C" void kernel_launch(void* const* d_in, const int* in_sizes, int n_in,
                              void* d_out, int out_size)
{
    int ix = 0, imask = 1, iwqkv = 2, ils = 5, iw1 = 6, iw2 = 8, iwproj = 9;
    int small[4] = {3, 4, 7, 10};
    int ns = 0;
    int sm_tmp[8];
    int fx = -1, fmask = -1, fwqkv = -1, fls = -1, fw1 = -1, fw2 = -1, fwp = -1;
    for (int i = 0; i < n_in; i++) {
        switch (in_sizes[i]) {
            case 37748736: fx = i; break;
            case 1327104:  fmask = i; break;
            case 786432:   fwqkv = i; break;
            case 16:       fls = i; break;
            case 1024:     fw1 = i; break;
            case 8192:     fw2 = i; break;
            case 262144:   fwp = i; break;
            case 512:      if (ns < 8) sm_tmp[ns++] = i; break;
            default: break;
        }
    }
    if (fx >= 0 && fmask >= 0 && fwqkv >= 0 && fls >= 0 && fw1 >= 0 &&
        fw2 >= 0 && fwp >= 0 && ns >= 4) {
        ix = fx; imask = fmask; iwqkv = fwqkv; ils = fls;
        iw1 = fw1; iw2 = fw2; iwproj = fwp;
        for (int t = 0; t < 4; t++) small[t] = sm_tmp[t];
    }

    const float* x           = (const float*)d_in[ix];
    const float* mask        = (const float*)d_in[imask];
    const float* w_qkv       = (const float*)d_in[iwqkv];
    const float* q_bias      = (const float*)d_in[small[0]];
    const float* v_bias      = (const float*)d_in[small[1]];
    const float* logit_scale = (const float*)d_in[ils];
    const float* w1          = (const float*)d_in[iw1];
    const float* b1          = (const float*)d_in[small[2]];
    const float* w2          = (const float*)d_in[iw2];
    const float* w_proj      = (const float*)d_in[iwproj];
    const float* b_proj      = (const float*)d_in[small[3]];
    float* out = (float*)d_out;
    (void)out_size;

    // 0) pre-split fp32 -> bf16 hi/lo
    split_kernel<0><<<4096, 256>>>(x, (int)(XN / 4));
    split_kernel<1><<<768, 256>>>(w_qkv, 3 * DIM * KDIM / 4);
    split_kernel<2><<<256, 256>>>(w_proj, DIM * KDIM / 4);

    // 1) CPB bias table (529 blocks, K-parallel)
    cpb_kernel<<<529, 128>>>(w1, b1, w2);

    // 2) QKV: (73728 x 512) @ (1536 x 512)^T — cp.async bf16 mma.sync
    {
        dim3 grid(1536 / 128, (BW * NTOK) / 128);
        gemm_b<0><<<grid, 256>>>(q_bias, v_bias, nullptr);
    }

    // 3) attention per (b,h) — smem-probs form, bf16-split output
    attn_kernel<<<BW * NH, 256>>>(mask, logit_scale);

    // 4) proj: (73728 x 512) @ (512 x 512)^T — cp.async bf16 mma.sync
    {
        dim3 grid(DIM / 128, (BW * NTOK) / 128);
        gemm_b<1><<<grid, 256>>>(b_proj, nullptr, out);
    }
}

// round 9
// speedup vs baseline: 1.8729x; 1.5173x over previous
#include <cuda_runtime.h>
#include <cuda_bf16.h>
#include <math.h>
#include <stdint.h>

// ---------------------------------------------------------------------------
// WindowAttention (Swin-V2) on GB300 — full-MMA pipeline:
//   cp.async bf16-split mma.sync GEMMs + mma.sync flash-style attention.
// ---------------------------------------------------------------------------

#define BW   512
#define NTOK 144
#define DIM  512
#define NH   16
#define HD   32
#define NWIN 64
#define KDIM 512
#define XN   ((size_t)BW * NTOK * DIM)       // 37748736

// device scratch — referenced ONLY from device code (host shadow-ptr trap)
__device__ float g_q[(size_t)BW * NH * NTOK * HD];
__device__ float g_k[(size_t)BW * NH * NTOK * HD];
__device__ float g_v[(size_t)BW * NH * NTOK * HD];
__device__ float g_cpb[NH * 529];

// pre-split bf16 operands
__device__ __nv_bfloat16 g_xhi[XN],  g_xlo[XN];        // x
__device__ __nv_bfloat16 g_ohi[XN],  g_olo[XN];        // attention output
__device__ __nv_bfloat16 g_wqhi[3 * DIM * KDIM], g_wqlo[3 * DIM * KDIM];
__device__ __nv_bfloat16 g_wphi[DIM * KDIM],     g_wplo[DIM * KDIM];

static __device__ __forceinline__ uint32_t smem_u32(const void* p) {
    uint32_t a;
    asm("{ .reg .u64 t; cvta.to.shared.u64 t, %1; cvt.u32.u64 %0, t; }"
        : "=r"(a) : "l"(p));
    return a;
}

#define LDM4(r, addr) \
    asm volatile("ldmatrix.sync.aligned.m8n8.x4.shared.b16 {%0,%1,%2,%3}, [%4];" \
                 : "=r"((r)[0]), "=r"((r)[1]), "=r"((r)[2]), "=r"((r)[3]) \
                 : "r"(addr))

#define MMA16816(d, a, b0, b1) \
    asm volatile("mma.sync.aligned.m16n8k16.row.col.f32.bf16.bf16.f32 " \
                 "{%0,%1,%2,%3}, {%4,%5,%6,%7}, {%8,%9}, {%0,%1,%2,%3};" \
                 : "+f"((d)[0]), "+f"((d)[1]), "+f"((d)[2]), "+f"((d)[3]) \
                 : "r"((a)[0]), "r"((a)[1]), "r"((a)[2]), "r"((a)[3]), \
                   "r"(b0), "r"(b1))

#define CP_ASYNC16(saddr, gptr) \
    asm volatile("cp.async.cg.shared.global [%0], [%1], 16;" \
                 :: "r"(saddr), "l"(gptr))
#define CP_COMMIT() asm volatile("cp.async.commit_group;" ::: "memory")
#define CP_WAIT1()  asm volatile("cp.async.wait_group 1;" ::: "memory")

__device__ __forceinline__ void split1(float v, __nv_bfloat16& h, __nv_bfloat16& l) {
    h = __float2bfloat16(v);
    l = __float2bfloat16(v - __bfloat162float(h));
}
__device__ __forceinline__ uint32_t pkbf(__nv_bfloat16 a, __nv_bfloat16 b) {
    return (uint32_t)__bfloat16_as_ushort(a) |
           ((uint32_t)__bfloat16_as_ushort(b) << 16);
}

// ---------------------------------------------------------------------------
// splitter: float -> bf16 hi + residual lo.  SEL: 0=x, 1=w_qkv, 2=w_proj
// ---------------------------------------------------------------------------
template <int SEL>
__global__ void split_kernel(const float* __restrict__ src, int n4)
{
    __nv_bfloat16* dhi = (SEL == 0) ? g_xhi : (SEL == 1) ? g_wqhi : g_wphi;
    __nv_bfloat16* dlo = (SEL == 0) ? g_xlo : (SEL == 1) ? g_wqlo : g_wplo;
    for (int i = blockIdx.x * blockDim.x + threadIdx.x; i < n4;
         i += gridDim.x * blockDim.x) {
        float4 v = ((const float4*)src)[i];
        __nv_bfloat16 h0, h1, h2, h3, l0, l1, l2, l3;
        split1(v.x, h0, l0); split1(v.y, h1, l1);
        split1(v.z, h2, l2); split1(v.w, h3, l3);
        ((ushort4*)dhi)[i] = make_ushort4(
            __bfloat16_as_ushort(h0), __bfloat16_as_ushort(h1),
            __bfloat16_as_ushort(h2), __bfloat16_as_ushort(h3));
        ((ushort4*)dlo)[i] = make_ushort4(
            __bfloat16_as_ushort(l0), __bfloat16_as_ushort(l1),
            __bfloat16_as_ushort(l2), __bfloat16_as_ushort(l3));
    }
}

// ---------------------------------------------------------------------------
// CPB MLP — one block per table entry, 128 threads split K
// ---------------------------------------------------------------------------
__global__ __launch_bounds__(128)
void cpb_kernel(const float* __restrict__ w1,
                const float* __restrict__ b1,
                const float* __restrict__ w2)
{
    __shared__ float part[4][NH];
    int idx = blockIdx.x;
    int tid = threadIdx.x;
    int lane = tid & 31;
    int w = tid >> 5;

    int a = idx / 23, bb = idx % 23;
    float ta = (float)(a - 11) * (8.0f / 11.0f);
    float tb = (float)(bb - 11) * (8.0f / 11.0f);
    float t0 = copysignf(log2f(fabsf(ta) + 1.0f) * (1.0f / 3.0f), ta);
    float t1 = copysignf(log2f(fabsf(tb) + 1.0f) * (1.0f / 3.0f), tb);

    float acc[NH];
#pragma unroll
    for (int h = 0; h < NH; h++) acc[h] = 0.0f;
#pragma unroll
    for (int kk = 0; kk < 4; kk++) {
        int k = tid + kk * 128;
        float hid = fmaf(t0, w1[2 * k], fmaf(t1, w1[2 * k + 1], b1[k]));
        hid = fmaxf(hid, 0.0f);
#pragma unroll
        for (int h = 0; h < NH; h++) acc[h] = fmaf(hid, w2[h * 512 + k], acc[h]);
    }
#pragma unroll
    for (int off = 16; off; off >>= 1)
#pragma unroll
        for (int h = 0; h < NH; h++)
            acc[h] += __shfl_xor_sync(0xffffffffu, acc[h], off);
    if (lane == 0)
#pragma unroll
        for (int h = 0; h < NH; h++) part[w][h] = acc[h];
    __syncthreads();
    if (tid < NH) {
        float s = part[0][tid] + part[1][tid] + part[2][tid] + part[3][tid];
        g_cpb[tid * 529 + idx] = 16.0f / (1.0f + __expf(-s));
    }
}

// ---------------------------------------------------------------------------
// cp.async 3-stage mma.sync GEMM (unchanged from R8)
// ---------------------------------------------------------------------------
#define CHUNKS 32
#define STG 16384
#define NSTAGE 3

template <int MODE>
__global__ __launch_bounds__(256)
void gemm_b(const float* __restrict__ biasA, const float* __restrict__ biasB,
            float* __restrict__ C)
{
    const __nv_bfloat16* __restrict__ Ahi = (MODE == 0) ? g_xhi : g_ohi;
    const __nv_bfloat16* __restrict__ Alo = (MODE == 0) ? g_xlo : g_olo;
    const __nv_bfloat16* __restrict__ Whi = (MODE == 0) ? g_wqhi : g_wphi;
    const __nv_bfloat16* __restrict__ Wlo = (MODE == 0) ? g_wqlo : g_wplo;

    __shared__ __align__(16) unsigned char sb[NSTAGE][STG];

    const int tid = threadIdx.x;
    const int lane = tid & 31;
    const int w = tid >> 5;
    const int wm = w & 1;
    const int wn = w >> 1;
    const int m0 = blockIdx.y * 128;
    const int n0 = blockIdx.x * 128;

    float acc[4][4][4];
#pragma unroll
    for (int i = 0; i < 4; i++)
#pragma unroll
        for (int j = 0; j < 4; j++)
#pragma unroll
            for (int r = 0; r < 4; r++) acc[i][j][r] = 0.0f;

    const int row = tid >> 1;
    const int kseg = tid & 1;
    const int aoff = (row >> 4) * 512 + (kseg * 2 + ((row >> 3) & 1)) * 128
                   + (row & 7) * 16;
    const int boff = (row >> 4) * 512 + (((row >> 3) & 1) * 2 + kseg) * 128
                   + (row & 7) * 16;
    const size_t ga = (size_t)(m0 + row) * KDIM + kseg * 8;
    const size_t gb = (size_t)(n0 + row) * KDIM + kseg * 8;

    auto issue_stage = [&](int c, int st) {
        uint32_t s = smem_u32(sb[st]);
        CP_ASYNC16(s + aoff,         (const char*)&Ahi[ga + c * 16]);
        CP_ASYNC16(s + 4096 + aoff,  (const char*)&Alo[ga + c * 16]);
        CP_ASYNC16(s + 8192 + boff,  (const char*)&Whi[gb + c * 16]);
        CP_ASYNC16(s + 12288 + boff, (const char*)&Wlo[gb + c * 16]);
        CP_COMMIT();
    };

    const uint32_t lmoff = (uint32_t)((lane >> 3) * 128 + (lane & 7) * 16);

    auto compute_stage = [&](int st) {
        uint32_t sbase = smem_u32(sb[st]);
        uint32_t a_lm = sbase + (uint32_t)(wm * 4) * 512u + lmoff;
        uint32_t b_lm = sbase + 8192u + (uint32_t)(wn * 2) * 512u + lmoff;

        uint32_t ahi[4][4], alo[4][4], bhi[2][4], blo[2][4];
#pragma unroll
        for (int ti = 0; ti < 4; ti++) LDM4(ahi[ti], a_lm + ti * 512);
#pragma unroll
        for (int g = 0; g < 2; g++) LDM4(bhi[g], b_lm + g * 512);
#pragma unroll
        for (int ti = 0; ti < 4; ti++)
#pragma unroll
            for (int tj = 0; tj < 4; tj++)
                MMA16816(acc[ti][tj], ahi[ti],
                         bhi[tj >> 1][(tj & 1) * 2], bhi[tj >> 1][(tj & 1) * 2 + 1]);
#pragma unroll
        for (int g = 0; g < 2; g++) LDM4(blo[g], b_lm + 4096 + g * 512);
#pragma unroll
        for (int ti = 0; ti < 4; ti++)
#pragma unroll
            for (int tj = 0; tj < 4; tj++)
                MMA16816(acc[ti][tj], ahi[ti],
                         blo[tj >> 1][(tj & 1) * 2], blo[tj >> 1][(tj & 1) * 2 + 1]);
#pragma unroll
        for (int ti = 0; ti < 4; ti++) LDM4(alo[ti], a_lm + 4096 + ti * 512);
#pragma unroll
        for (int ti = 0; ti < 4; ti++)
#pragma unroll
            for (int tj = 0; tj < 4; tj++)
                MMA16816(acc[ti][tj], alo[ti],
                         bhi[tj >> 1][(tj & 1) * 2], bhi[tj >> 1][(tj & 1) * 2 + 1]);
    };

    issue_stage(0, 0);
    issue_stage(1, 1);

    int st = 0, st2 = 2;
    for (int c = 0; c < CHUNKS; c++) {
        CP_WAIT1();
        __syncthreads();
        compute_stage(st);
        if (c + 2 < CHUNKS) issue_stage(c + 2, st2);
        st = (st + 1 == NSTAGE) ? 0 : st + 1;
        st2 = (st2 + 1 == NSTAGE) ? 0 : st2 + 1;
    }

#pragma unroll
    for (int ti = 0; ti < 4; ti++) {
#pragma unroll
        for (int half = 0; half < 2; half++) {
            int m = m0 + wm * 64 + ti * 16 + (lane >> 2) + half * 8;
            int bwin = 0, nt = 0;
            if (MODE == 0) { bwin = m / NTOK; nt = m - bwin * NTOK; }
#pragma unroll
            for (int tj = 0; tj < 4; tj++) {
                int n = n0 + wn * 32 + tj * 8 + (lane & 3) * 2;
                float v0 = acc[ti][tj][half * 2 + 0];
                float v1 = acc[ti][tj][half * 2 + 1];
                if (MODE == 0) {
                    int which = n >> 9;
                    int cc = n & 511;
                    int hh = cc >> 5;
                    int dd = cc & 31;
                    float b0 = (which == 0) ? biasA[cc]
                             : (which == 2 ? biasB[cc] : 0.0f);
                    float b1 = (which == 0) ? biasA[cc + 1]
                             : (which == 2 ? biasB[cc + 1] : 0.0f);
                    float* dst = (which == 0) ? g_q : (which == 1 ? g_k : g_v);
                    *(float2*)&dst[((((size_t)bwin * NH + hh) * NTOK) + nt) * HD + dd] =
                        make_float2(v0 + b0, v1 + b1);
                } else {
                    *(float2*)&C[(size_t)m * DIM + n] =
                        make_float2(v0 + biasA[n], v1 + biasA[n + 1]);
                }
            }
        }
    }
}

// ---------------------------------------------------------------------------
// MMA attention: one block per (b,h), 128 threads (4 warps), 9 m-tiles of 16.
// Dynamic smem 57412B: khi klo vhi vlo qhi qlo (9216B each, ldmatrix-block
// layout; v stored transposed [d][j]) + bias table (529 f32).
// QK^T: 3-pass Markidis; softmax in fragment layout; S-frags reused directly
// as PV A-frags (bf16 hi/lo); output written as bf16 hi/lo split.
// ---------------------------------------------------------------------------
#define ASM_K  0
#define ASM_KL 9216
#define ASM_V  18432
#define ASM_VL 27648
#define ASM_Q  36864
#define ASM_QL 46080
#define ASM_BS 55296
#define ATT_SMEM (55296 + 2116)

__global__ __launch_bounds__(128)
void attn_kernel(const float* __restrict__ mask,
                 const float* __restrict__ logit_scale)
{
    extern __shared__ char smc[];
    float* bs = (float*)(smc + ASM_BS);

    int bid = blockIdx.x;
    int b = bid >> 4;
    int h = bid & 15;
    int tid = threadIdx.x;
    int w = tid >> 5;
    int lane = tid & 31;

    for (int t = tid; t < 529; t += 128) bs[t] = g_cpb[h * 529 + t];

    size_t base = (size_t)bid * (NTOK * HD);
    float scale = __expf(fminf(logit_scale[h], 4.605170185988092f));

    // prepass: normalize+split q (scale folded), k; split v transposed
    for (int r = tid; r < NTOK; r += 128) {
        float buf[HD];
        // q
#pragma unroll
        for (int p = 0; p < 8; p++)
            *(float4*)&buf[p * 4] = *(const float4*)&g_q[base + (size_t)r * HD + p * 4];
        float ss = 0.0f;
#pragma unroll
        for (int d = 0; d < HD; d++) ss = fmaf(buf[d], buf[d], ss);
        float inv = scale / fmaxf(sqrtf(ss), 1e-12f);
#pragma unroll
        for (int d = 0; d < HD; d++) {
            __nv_bfloat16 hh, ll;
            split1(buf[d] * inv, hh, ll);
            int off = (r >> 4) * 1024 + (d >> 4) * 512
                    + (((d >> 3) & 1) * 2 + ((r >> 3) & 1)) * 128
                    + (r & 7) * 16 + (d & 7) * 2;
            *(__nv_bfloat16*)(smc + ASM_Q + off) = hh;
            *(__nv_bfloat16*)(smc + ASM_QL + off) = ll;
        }
        // k
#pragma unroll
        for (int p = 0; p < 8; p++)
            *(float4*)&buf[p * 4] = *(const float4*)&g_k[base + (size_t)r * HD + p * 4];
        ss = 0.0f;
#pragma unroll
        for (int d = 0; d < HD; d++) ss = fmaf(buf[d], buf[d], ss);
        inv = 1.0f / fmaxf(sqrtf(ss), 1e-12f);
#pragma unroll
        for (int d = 0; d < HD; d++) {
            __nv_bfloat16 hh, ll;
            split1(buf[d] * inv, hh, ll);
            int off = (r >> 4) * 1024 + (d >> 4) * 512
                    + (((r >> 3) & 1) * 2 + ((d >> 3) & 1)) * 128
                    + (r & 7) * 16 + (d & 7) * 2;
            *(__nv_bfloat16*)(smc + ASM_K + off) = hh;
            *(__nv_bfloat16*)(smc + ASM_KL + off) = ll;
        }
        // v — transposed [d][j=r]
#pragma unroll
        for (int p = 0; p < 8; p++)
            *(float4*)&buf[p * 4] = *(const float4*)&g_v[base + (size_t)r * HD + p * 4];
#pragma unroll
        for (int d = 0; d < HD; d++) {
            __nv_bfloat16 hh, ll;
            split1(buf[d], hh, ll);
            int off = (d >> 4) * 4608 + (r >> 4) * 512
                    + (((d >> 3) & 1) * 2 + ((r >> 3) & 1)) * 128
                    + (d & 7) * 16 + (r & 7) * 2;
            *(__nv_bfloat16*)(smc + ASM_V + off) = hh;
            *(__nv_bfloat16*)(smc + ASM_VL + off) = ll;
        }
    }
    __syncthreads();

    const float* mbase = mask + (size_t)(b & (NWIN - 1)) * (NTOK * NTOK);
    const uint32_t lmoff = (uint32_t)((lane >> 3) * 128 + (lane & 7) * 16);
    const uint32_t kh_b = smem_u32(smc + ASM_K) + lmoff;
    const uint32_t kl_b = smem_u32(smc + ASM_KL) + lmoff;
    const uint32_t vh_b = smem_u32(smc + ASM_V) + lmoff;
    const uint32_t vl_b = smem_u32(smc + ASM_VL) + lmoff;
    const uint32_t qh_b = smem_u32(smc + ASM_Q) + lmoff;
    const uint32_t ql_b = smem_u32(smc + ASM_QL) + lmoff;

    for (int mt = w; mt < 9; mt += 4) {
        float s[18][4];
#pragma unroll
        for (int tj = 0; tj < 18; tj++)
#pragma unroll
            for (int r = 0; r < 4; r++) s[tj][r] = 0.0f;

        uint32_t aq[2][4], aql[2][4];
#pragma unroll
        for (int u = 0; u < 2; u++) {
            LDM4(aq[u], qh_b + mt * 1024 + u * 512);
            LDM4(aql[u], ql_b + mt * 1024 + u * 512);
        }
#pragma unroll
        for (int t2 = 0; t2 < 9; t2++) {
            uint32_t kbh[2][4], kbl[2][4];
#pragma unroll
            for (int u = 0; u < 2; u++) {
                LDM4(kbh[u], kh_b + t2 * 1024 + u * 512);
                LDM4(kbl[u], kl_b + t2 * 1024 + u * 512);
            }
#pragma unroll
            for (int u = 0; u < 2; u++)
#pragma unroll
                for (int hf = 0; hf < 2; hf++) {
                    int tj = t2 * 2 + hf;
                    MMA16816(s[tj], aq[u], kbh[u][hf * 2], kbh[u][hf * 2 + 1]);
                    MMA16816(s[tj], aq[u], kbl[u][hf * 2], kbl[u][hf * 2 + 1]);
                    MMA16816(s[tj], aql[u], kbh[u][hf * 2], kbh[u][hf * 2 + 1]);
                }
        }

        // softmax in fragment layout
        int r0 = mt * 16 + (lane >> 2);
        int r1 = r0 + 8;
        int yi0 = r0 / 12, xi0 = r0 - yi0 * 12;
        int yi1 = r1 / 12, xi1 = r1 - yi1 * 12;
        float mx0 = -1e30f, mx1 = -1e30f;
#pragma unroll
        for (int tj = 0; tj < 18; tj++) {
            int j0 = tj * 8 + (lane & 3) * 2;
            int j1 = j0 + 1;
            int yj0 = j0 / 12, xj0 = j0 - yj0 * 12;
            int yj1 = j1 / 12, xj1 = j1 - yj1 * 12;
            float2 mk0 = *(const float2*)&mbase[r0 * NTOK + j0];
            float2 mk1 = *(const float2*)&mbase[r1 * NTOK + j0];
            s[tj][0] += bs[(yi0 - yj0 + 11) * 23 + (xi0 - xj0 + 11)] + mk0.x;
            s[tj][1] += bs[(yi0 - yj1 + 11) * 23 + (xi0 - xj1 + 11)] + mk0.y;
            s[tj][2] += bs[(yi1 - yj0 + 11) * 23 + (xi1 - xj0 + 11)] + mk1.x;
            s[tj][3] += bs[(yi1 - yj1 + 11) * 23 + (xi1 - xj1 + 11)] + mk1.y;
            mx0 = fmaxf(mx0, fmaxf(s[tj][0], s[tj][1]));
            mx1 = fmaxf(mx1, fmaxf(s[tj][2], s[tj][3]));
        }
        mx0 = fmaxf(mx0, __shfl_xor_sync(0xffffffffu, mx0, 1));
        mx0 = fmaxf(mx0, __shfl_xor_sync(0xffffffffu, mx0, 2));
        mx1 = fmaxf(mx1, __shfl_xor_sync(0xffffffffu, mx1, 1));
        mx1 = fmaxf(mx1, __shfl_xor_sync(0xffffffffu, mx1, 2));

        float sum0 = 0.0f, sum1 = 0.0f;
#pragma unroll
        for (int tj = 0; tj < 18; tj++) {
            s[tj][0] = __expf(s[tj][0] - mx0);
            s[tj][1] = __expf(s[tj][1] - mx0);
            s[tj][2] = __expf(s[tj][2] - mx1);
            s[tj][3] = __expf(s[tj][3] - mx1);
            sum0 += s[tj][0] + s[tj][1];
            sum1 += s[tj][2] + s[tj][3];
        }
        sum0 += __shfl_xor_sync(0xffffffffu, sum0, 1);
        sum0 += __shfl_xor_sync(0xffffffffu, sum0, 2);
        sum1 += __shfl_xor_sync(0xffffffffu, sum1, 1);
        sum1 += __shfl_xor_sync(0xffffffffu, sum1, 2);
        float inv0 = 1.0f / sum0;
        float inv1 = 1.0f / sum1;

        // PV: S-frag pairs ARE the A-frags (pack to bf16 hi/lo per k16)
        float o[4][4];
#pragma unroll
        for (int nd = 0; nd < 4; nd++)
#pragma unroll
            for (int r = 0; r < 4; r++) o[nd][r] = 0.0f;

#pragma unroll
        for (int t = 0; t < 9; t++) {
            uint32_t ph[4], pl[4];
#pragma unroll
            for (int rg = 0; rg < 4; rg++) {
                float a = s[t * 2 + (rg >> 1)][(rg & 1) * 2 + 0];
                float c = s[t * 2 + (rg >> 1)][(rg & 1) * 2 + 1];
                __nv_bfloat16 ha, la, hc, lc;
                split1(a, ha, la);
                split1(c, hc, lc);
                ph[rg] = pkbf(ha, hc);
                pl[rg] = pkbf(la, lc);
            }
            // NOTE frag order: reg0,1 = rows r0,r1 cols 0-7 (n-grp 2t);
            // reg2,3 = cols 8-15 (n-grp 2t+1) -> rg mapping: rg0=s[2t]{c0,c1},
            // rg1=s[2t]{c2,c3}, rg2=s[2t+1]{c0,c1}, rg3=s[2t+1]{c2,c3}
            uint32_t vbh[2][4], vbl[2][4];
#pragma unroll
            for (int u = 0; u < 2; u++) {
                LDM4(vbh[u], vh_b + u * 4608 + t * 512);
                LDM4(vbl[u], vl_b + u * 4608 + t * 512);
            }
#pragma unroll
            for (int nd = 0; nd < 4; nd++) {
                int u = nd >> 1, rr = (nd & 1) * 2;
                MMA16816(o[nd], ph, vbh[u][rr], vbh[u][rr + 1]);
                MMA16816(o[nd], pl, vbh[u][rr], vbh[u][rr + 1]);
                MMA16816(o[nd], ph, vbl[u][rr], vbl[u][rr + 1]);
            }
        }

        // output: bf16 hi/lo split
        size_t ob = ((size_t)b * NTOK) * DIM + h * HD;
#pragma unroll
        for (int nd = 0; nd < 4; nd++) {
            int d = nd * 8 + (lane & 3) * 2;
            float a0 = o[nd][0] * inv0, a1 = o[nd][1] * inv0;
            float a2 = o[nd][2] * inv1, a3 = o[nd][3] * inv1;
            __nv_bfloat16 h0, l0, h1, l1, h2, l2, h3, l3;
            split1(a0, h0, l0); split1(a1, h1, l1);
            split1(a2, h2, l2); split1(a3, h3, l3);
            size_t i0 = ob + (size_t)r0 * DIM + d;
            size_t i1 = ob + (size_t)r1 * DIM + d;
            *(ushort2*)&g_ohi[i0] = make_ushort2(__bfloat16_as_ushort(h0),
                                                 __bfloat16_as_ushort(h1));
            *(ushort2*)&g_olo[i0] = make_ushort2(__bfloat16_as_ushort(l0),
                                                 __bfloat16_as_ushort(l1));
            *(ushort2*)&g_ohi[i1] = make_ushort2(__bfloat16_as_ushort(h2),
                                                 __bfloat16_as_ushort(h3));
            *(ushort2*)&g_olo[i1] = make_ushort2(__bfloat16_as_ushort(l2),
                                                 __bfloat16_as_ushort(l3));
        }
    }
}

// ---------------------------------------------------------------------------
// launch — size-based input resolution (order-robust)
// ---------------------------------------------------------------------------
extern "C" void kernel_launch(void* const* d_in, const int* in_sizes, int n_in,
                              void* d_out, int out_size)
{
    int ix = 0, imask = 1, iwqkv = 2, ils = 5, iw1 = 6, iw2 = 8, iwproj = 9;
    int small[4] = {3, 4, 7, 10};
    int ns = 0;
    int sm_tmp[8];
    int fx = -1, fmask = -1, fwqkv = -1, fls = -1, fw1 = -1, fw2 = -1, fwp = -1;
    for (int i = 0; i < n_in; i++) {
        switch (in_sizes[i]) {
            case 37748736: fx = i; break;
            case 1327104:  fmask = i; break;
            case 786432:   fwqkv = i; break;
            case 16:       fls = i; break;
            case 1024:     fw1 = i; break;
            case 8192:     fw2 = i; break;
            case 262144:   fwp = i; break;
            case 512:      if (ns < 8) sm_tmp[ns++] = i; break;
            default: break;
        }
    }
    if (fx >= 0 && fmask >= 0 && fwqkv >= 0 && fls >= 0 && fw1 >= 0 &&
        fw2 >= 0 && fwp >= 0 && ns >= 4) {
        ix = fx; imask = fmask; iwqkv = fwqkv; ils = fls;
        iw1 = fw1; iw2 = fw2; iwproj = fwp;
        for (int t = 0; t < 4; t++) small[t] = sm_tmp[t];
    }

    const float* x           = (const float*)d_in[ix];
    const float* mask        = (const float*)d_in[imask];
    const float* w_qkv       = (const float*)d_in[iwqkv];
    const float* q_bias      = (const float*)d_in[small[0]];
    const float* v_bias      = (const float*)d_in[small[1]];
    const float* logit_scale = (const float*)d_in[ils];
    const float* w1          = (const float*)d_in[iw1];
    const float* b1          = (const float*)d_in[small[2]];
    const float* w2          = (const float*)d_in[iw2];
    const float* w_proj      = (const float*)d_in[iwproj];
    const float* b_proj      = (const float*)d_in[small[3]];
    float* out = (float*)d_out;
    (void)out_size;

    cudaFuncSetAttribute(attn_kernel,
                         cudaFuncAttributeMaxDynamicSharedMemorySize,
                         ATT_SMEM);

    // 0) pre-split fp32 -> bf16 hi/lo
    split_kernel<0><<<4096, 256>>>(x, (int)(XN / 4));
    split_kernel<1><<<768, 256>>>(w_qkv, 3 * DIM * KDIM / 4);
    split_kernel<2><<<256, 256>>>(w_proj, DIM * KDIM / 4);

    // 1) CPB bias table
    cpb_kernel<<<529, 128>>>(w1, b1, w2);

    // 2) QKV: (73728 x 512) @ (1536 x 512)^T — cp.async bf16 mma.sync
    {
        dim3 grid(1536 / 128, (BW * NTOK) / 128);
        gemm_b<0><<<grid, 256>>>(q_bias, v_bias, nullptr);
    }

    // 3) attention per (b,h) — mma.sync flash-style
    attn_kernel<<<BW * NH, 128, ATT_SMEM>>>(mask, logit_scale);

    // 4) proj: (73728 x 512) @ (512 x 512)^T — cp.async bf16 mma.sync
    {
        dim3 grid(DIM / 128, (BW * NTOK) / 128);
        gemm_b<1><<<grid, 256>>>(b_proj, nullptr, out);
    }
}